// round 11
// baseline (speedup 1.0000x reference)
#include <cuda_runtime.h>
#include <math.h>

// Global accumulator + completion counter, zero-initialized at module load;
// the finalizer warp resets both each run so graph replays are deterministic.
__device__ float g_acc;
__device__ unsigned int g_ctr;

// ---------------------------------------------------------------------------
// Warp-collective: exp(cosine) of one row pair (D=1024, 256 float4s).
// All lanes return the reduced value (xor-tree leaves it everywhere).
// ---------------------------------------------------------------------------
__device__ __forceinline__ float exp_cos_row(
    const float* __restrict__ a, const float* __restrict__ b,
    size_t row, int lane)
{
    const float4* __restrict__ a4 = reinterpret_cast<const float4*>(a) + row * 256;
    const float4* __restrict__ b4 = reinterpret_cast<const float4*>(b) + row * 256;

    float dot = 0.0f, na2 = 0.0f, nb2 = 0.0f;
#pragma unroll
    for (int i = 0; i < 8; i++) {
        float4 va = __ldcs(a4 + lane + i * 32);
        float4 vb = __ldcs(b4 + lane + i * 32);
        dot = fmaf(va.x, vb.x, dot); na2 = fmaf(va.x, va.x, na2); nb2 = fmaf(vb.x, vb.x, nb2);
        dot = fmaf(va.y, vb.y, dot); na2 = fmaf(va.y, va.y, na2); nb2 = fmaf(vb.y, vb.y, nb2);
        dot = fmaf(va.z, vb.z, dot); na2 = fmaf(va.z, va.z, na2); nb2 = fmaf(vb.z, vb.z, nb2);
        dot = fmaf(va.w, vb.w, dot); na2 = fmaf(va.w, va.w, na2); nb2 = fmaf(vb.w, vb.w, nb2);
    }
#pragma unroll
    for (int off = 16; off > 0; off >>= 1) {
        dot += __shfl_xor_sync(0xffffffffu, dot, off);
        na2 += __shfl_xor_sync(0xffffffffu, na2, off);
        nb2 += __shfl_xor_sync(0xffffffffu, nb2, off);
    }
    float denom = fmaxf(sqrtf(na2) * sqrtf(nb2), 1e-8f);
    return expf(dot / denom);
}

// ---------------------------------------------------------------------------
// Warp-per-item kernel. Each warp streams its item's 25 row pairs (contiguous
// 200 KB), computes the per-item loss fully in registers, then signals:
//   lane0: relaxed atomicAdd(g_acc, loss)  [4096 adds @ ~36/us: trivial]
//          red.release.gpu on g_ctr        [0.02 ops/cyc: 50x below the
//                                           single-address cap R9 saturated]
// The warp owning the last item polls g_ctr (acquire + nanosleep), then
// publishes out[0] and resets the scratch. No second kernel, no segment
// scratch, no per-row atomics.
// ---------------------------------------------------------------------------
__global__ void __launch_bounds__(64) contrastive_item_kernel(
    const float* __restrict__ q_pos, const float* __restrict__ i_pos,
    const float* __restrict__ q_neg, const float* __restrict__ i_neg,
    float* __restrict__ out, int n_items)
{
    const int item = (blockIdx.x * blockDim.x + threadIdx.x) >> 5;
    const int lane = threadIdx.x & 31;

    if (item < n_items) {
        float psum = 0.0f;
#pragma unroll
        for (int r = 0; r < 2; r++)
            psum += exp_cos_row(q_pos, i_pos, (size_t)item * 2 + r, lane);

        float nsum = 0.0f;
        for (int r = 0; r < 23; r++)
            nsum += exp_cos_row(q_neg, i_neg, (size_t)item * 23 + r, lane);

        if (lane == 0) {
            float loss = (nsum - psum) / (psum + nsum + 0.001f);
            atomicAdd(&g_acc, loss);   // relaxed, rate-trivial
            asm volatile("red.release.gpu.global.add.u32 [%0], %1;"
                         :: "l"(&g_ctr), "r"(1u) : "memory");
        }
    }

    // ---- Finalizer: the warp that owns the last item, lane 0 only ----
    if (item != n_items - 1 || lane != 0) return;

    unsigned int c;
    do {
        asm volatile("ld.acquire.gpu.global.u32 %0, [%1];"
                     : "=r"(c) : "l"(&g_ctr) : "memory");
        if (c < (unsigned int)n_items) __nanosleep(64);
    } while (c < (unsigned int)n_items);

    float v;
    asm volatile("ld.acquire.gpu.global.f32 %0, [%1];"
                 : "=f"(v) : "l"(&g_acc) : "memory");
    out[0] = v;
    g_acc = 0.0f;      // reset for next graph replay
    g_ctr = 0u;
}

// ---------------------------------------------------------------------------
// Inputs (metadata order):
//   0: question_embeddings_pos  [2B, 1024] f32
//   1: question_embeddings_neg  [23B, 1024] f32
//   2: pos_image_embeddings     [2B, 1024] f32
//   3: neg_image_embeddings     [23B, 1024] f32
//   4: batch_size (int scalar)
// Output: f32 scalar.
// ---------------------------------------------------------------------------
extern "C" void kernel_launch(void* const* d_in, const int* in_sizes, int n_in,
                              void* d_out, int out_size) {
    const float* q_pos = (const float*)d_in[0];
    const float* q_neg = (const float*)d_in[1];
    const float* i_pos = (const float*)d_in[2];
    const float* i_neg = (const float*)d_in[3];
    float* out = (float*)d_out;

    const int D = 1024;
    const int B = in_sizes[0] / (2 * D);   // n_items

    // 64-thread blocks (2 warps = 2 items): 2048 blocks for B=4096 -> fine-
    // grained dynamic balancing across 148 SMs.
    const int threads = 64;
    const int blocks = (B * 32 + threads - 1) / threads;
    contrastive_item_kernel<<<blocks, threads>>>(
        q_pos, i_pos, q_neg, i_neg, out, B);
}